// round 5
// baseline (speedup 1.0000x reference)
#include <cuda_runtime.h>

// Reference degenerates to: mean over (b, j) of (true[b,10j] - pred[b,10j])^2.
//
// R4 insight: stride-10 gather still transfers the FULL tensor at DRAM
// granularity (every 64B chunk contains a sample), measured 67.5 MB. So read
// everything coalesced (float4) and select sample lanes arithmetically:
// a float4 at column c..c+3 contains a sample iff (c % 10) in {0,7,8,9}.
// 8192 % 4 == 0 -> float4 never crosses a row boundary.

#define ROWS    1024
#define NFRM    8192
#define NSAMP   820
#define F4ROW   (NFRM / 4)            // 2048 float4 per row (power of two)
#define NBLK    2048
#define NTHR    256
#define KPT     4                     // float4s per thread; 2048*256*4 = 2^21 exactly
#define SCALE   1073741824.0          // 2^30

__device__ unsigned long long g_acc = 0ULL;
__device__ unsigned int       g_cnt = 0u;

__global__ __launch_bounds__(NTHR)
void mse_fused_kernel(const float4* __restrict__ tf4,
                      const float4* __restrict__ pf4,
                      float* __restrict__ out) {
    const unsigned base = blockIdx.x * (NTHR * KPT) + threadIdx.x;

    unsigned q[KPT];
    float4 a[KPT], b[KPT];
#pragma unroll
    for (int k = 0; k < KPT; k++) q[k] = base + k * NTHR;

    // Fully coalesced front-batched loads: warp reads 128B per LDG.128 phase.
#pragma unroll
    for (int k = 0; k < KPT; k++) a[k] = __ldg(tf4 + q[k]);
#pragma unroll
    for (int k = 0; k < KPT; k++) b[k] = __ldg(pf4 + q[k]);

    float acc = 0.0f;
#pragma unroll
    for (int k = 0; k < KPT; k++) {
        unsigned col = 4u * (q[k] & (F4ROW - 1u));   // column of .x within row
        unsigned r = col % 10u;                       // sample lane selector
        float d = 0.0f;
        if (r == 0u)      d = a[k].x - b[k].x;
        else if (r == 9u) d = a[k].y - b[k].y;
        else if (r == 8u) d = a[k].z - b[k].z;
        else if (r == 7u) d = a[k].w - b[k].w;
        acc = fmaf(d, d, acc);
    }

    // Deterministic block reduction: warp shuffle + shared across 8 warps.
    __shared__ float sm[NTHR / 32];
#pragma unroll
    for (int off = 16; off > 0; off >>= 1)
        acc += __shfl_down_sync(0xFFFFFFFFu, acc, off);
    if ((threadIdx.x & 31) == 0) sm[threadIdx.x >> 5] = acc;
    __syncthreads();

    if (threadIdx.x == 0) {
        float v = sm[0];
#pragma unroll
        for (int w = 1; w < NTHR / 32; w++) v += sm[w];

        // Fixed-point: integer adds are associative => deterministic.
        long long qfx = llrint((double)v * SCALE);
        atomicAdd(&g_acc, (unsigned long long)qfx);
        __threadfence();
        unsigned int old = atomicAdd(&g_cnt, 1u);
        if (old == (unsigned int)(gridDim.x - 1)) {
            unsigned long long total = atomicAdd(&g_acc, 0ULL);
            out[0] = (float)(((double)(long long)total / SCALE)
                             / (double)((long long)ROWS * NSAMP));
            g_cnt = 0u;      // reset for next graph replay
            g_acc = 0ULL;
        }
    }
}

extern "C" void kernel_launch(void* const* d_in, const int* in_sizes, int n_in,
                              void* d_out, int out_size) {
    const float4* tf4 = (const float4*)d_in[0];   // true_frames  (1024, 8192)
    const float4* pf4 = (const float4*)d_in[1];   // predicted_frames
    float* out = (float*)d_out;

    mse_fused_kernel<<<NBLK, NTHR>>>(tf4, pf4, out);
}

// round 7
// speedup vs baseline: 1.1860x; 1.1860x over previous
#include <cuda_runtime.h>

// Reference degenerates to: mean over (b, j) of (true[b,10j] - pred[b,10j])^2.
//
// R5 resubmit (previous round failed with cudaErrorSystemNotReady during
// container bring-up — infra, not kernel). Theory: warm-L2 regime; binder was
// L1tex wavefronts (scalar stride-10 warp-LDG = 32 sector-wavefronts). Fix:
// each lane loads the ALIGNED float4 containing its sample -> same 32B-sector
// traffic (53.7MB), but lanes coalesce at line grain: ~10 wavefronts/warp.
// col = 10j; 10j % 4 alternates {0,2} -> sample is .x (j even) or .z (j odd).

#define ROWS    1024
#define NFRM    8192
#define F4ROW   (NFRM / 4)           // 2048 float4 per row
#define NSAMP   820
#define NBLK    820                  // 820*256*4 = 839680 samples exactly
#define NTHR    256
#define KPT     4
#define SCALE   1073741824.0         // 2^30

__device__ unsigned long long g_acc = 0ULL;
__device__ unsigned int       g_cnt = 0u;

__global__ __launch_bounds__(NTHR)
void mse_fused_kernel(const float4* __restrict__ tf4,
                      const float4* __restrict__ pf4,
                      float* __restrict__ out) {
    const unsigned base = blockIdx.x * (NTHR * KPT) + threadIdx.x;

    unsigned chunk[KPT];
    unsigned odd[KPT];
#pragma unroll
    for (int k = 0; k < KPT; k++) {
        unsigned i   = base + k * NTHR;          // global sample id
        unsigned row = i / NSAMP;                // umulhi-div
        unsigned j   = i - row * NSAMP;          // sample within row
        unsigned col = 10u * j;                  // column of the sample
        chunk[k] = row * F4ROW + (col >> 2);     // aligned float4 index
        odd[k]   = j & 1u;                       // component: 0 -> .x, 1 -> .z
    }

    // Front-batched LDG.128s; warp spans 10 lines -> ~10 wavefronts/request.
    float4 a[KPT], b[KPT];
#pragma unroll
    for (int k = 0; k < KPT; k++) a[k] = __ldg(tf4 + chunk[k]);
#pragma unroll
    for (int k = 0; k < KPT; k++) b[k] = __ldg(pf4 + chunk[k]);

    float acc = 0.0f;
#pragma unroll
    for (int k = 0; k < KPT; k++) {
        float av = odd[k] ? a[k].z : a[k].x;
        float bv = odd[k] ? b[k].z : b[k].x;
        float d = av - bv;
        acc = fmaf(d, d, acc);
    }

    // Deterministic block reduction: warp shuffle + shared across 8 warps.
    __shared__ float sm[NTHR / 32];
#pragma unroll
    for (int off = 16; off > 0; off >>= 1)
        acc += __shfl_down_sync(0xFFFFFFFFu, acc, off);
    if ((threadIdx.x & 31) == 0) sm[threadIdx.x >> 5] = acc;
    __syncthreads();

    if (threadIdx.x == 0) {
        float v = sm[0];
#pragma unroll
        for (int w = 1; w < NTHR / 32; w++) v += sm[w];

        // Fixed-point: integer adds are associative => deterministic.
        long long qfx = llrint((double)v * SCALE);
        atomicAdd(&g_acc, (unsigned long long)qfx);
        __threadfence();
        unsigned int old = atomicAdd(&g_cnt, 1u);
        if (old == (unsigned int)(gridDim.x - 1)) {
            unsigned long long total = atomicAdd(&g_acc, 0ULL);
            out[0] = (float)(((double)(long long)total / SCALE)
                             / (double)((long long)ROWS * NSAMP));
            g_cnt = 0u;      // reset for next graph replay
            g_acc = 0ULL;
        }
    }
}

extern "C" void kernel_launch(void* const* d_in, const int* in_sizes, int n_in,
                              void* d_out, int out_size) {
    const float4* tf4 = (const float4*)d_in[0];   // true_frames  (1024, 8192)
    const float4* pf4 = (const float4*)d_in[1];   // predicted_frames
    float* out = (float*)d_out;

    mse_fused_kernel<<<NBLK, NTHR>>>(tf4, pf4, out);
}